// round 13
// baseline (speedup 1.0000x reference)
#include <cuda_runtime.h>

#define BATCH 16
#define HW (1 << 20)
#define BINS 2048               // 11-bit quantization (rel_err 2.3e-4 validated in R12)
#define CPB 64                  // CTAs per batch -> grid 1024 (~one wave)
#define NT 256

// percentile ranks, n = 1048576 (linear interp):
// blk: 0.25*v[10485] + 0.75*v[10486] ; wht: 0.75*v[1038089] + 0.25*v[1038090]
#define RANK0 10485u
#define RANK1 10486u
#define RANK2 1038089u
#define RANK3 1038090u

// ---------------- device scratch ----------------
__device__ unsigned g_hist[BATCH][BINS];   // 128 KB, L2-resident
__device__ float    g_blk[BATCH];
__device__ float    g_mult[BATCH];
__device__ unsigned g_flag[BATCH];         // monotonic epoch counters (never reset)

// ------------- single fused kernel: hist -> in-kernel batch sync -> select -> apply -------------
__global__ void __launch_bounds__(NT) k_fused(const float* __restrict__ img,
                                              const float* __restrict__ mat,
                                              float* __restrict__ out) {
    __shared__ unsigned sh[BINS];
    __shared__ unsigned s_red[NT / 32];
    __shared__ unsigned s_total;
    __shared__ float s_vals[4];
    __shared__ float s_bm[2];
    __shared__ unsigned s_init;

    const int bid = blockIdx.x;
    const int b = bid / CPB;
    const int s = bid % CPB;
    const int tid = threadIdx.x;
    const int lane = tid & 31;
    const int wid = tid >> 5;

    // Epoch snapshot. Happens strictly BEFORE this CTA's hist flush, and the
    // producer bumps only after ALL batch flushes -> snapshot always pre-bump.
    if (tid == 0) s_init = __ldcg(&g_flag[b]);

    for (int j = tid; j < BINS; j += NT) sh[j] = 0u;
    __syncthreads();

    // ---------------- phase 1: histogram own 16K-pixel slice ----------------
    const float c0 = mat[0], c1 = mat[1], c2 = mat[2];
    const size_t base = (size_t)b * 3 * HW;
    const float4* __restrict__ R  = (const float4*)(img + base);
    const float4* __restrict__ G  = (const float4*)(img + base + HW);
    const float4* __restrict__ Bc = (const float4*)(img + base + 2 * (size_t)HW);

    const int per_cta = (HW / 4) / CPB;      // 4096 float4
    const int off = s * per_cta;

    #pragma unroll 4
    for (int i = tid; i < per_cta; i += NT) {
        float4 r = R[off + i];
        float4 g = G[off + i];
        float4 v = Bc[off + i];
        float y0 = c0 * r.x + c1 * g.x + c2 * v.x;
        float y1 = c0 * r.y + c1 * g.y + c2 * v.y;
        float y2 = c0 * r.z + c1 * g.z + c2 * v.z;
        float y3 = c0 * r.w + c1 * g.w + c2 * v.w;
        unsigned q0 = min((unsigned)(y0 * 2048.0f), BINS - 1u);
        unsigned q1 = min((unsigned)(y1 * 2048.0f), BINS - 1u);
        unsigned q2 = min((unsigned)(y2 * 2048.0f), BINS - 1u);
        unsigned q3 = min((unsigned)(y3 * 2048.0f), BINS - 1u);
        atomicAdd(&sh[q0], 1u);
        atomicAdd(&sh[q1], 1u);
        atomicAdd(&sh[q2], 1u);
        atomicAdd(&sh[q3], 1u);
    }
    __syncthreads();

    for (int j = tid; j < BINS; j += NT) {
        unsigned v = sh[j];
        if (v) atomicAdd(&g_hist[b][j], v);
    }

    if (s == 0) {
        // ---------------- producer: fence-free completion + select ----------------
        const unsigned* __restrict__ h = g_hist[b];
        const int W = BINS / NT;             // 8 bins per thread
        const int sbase = tid * W;
        unsigned bins[BINS / NT];
        unsigned local;

        for (;;) {                           // monotone sum == HW <=> all flushes visible
            local = 0;
            #pragma unroll
            for (int j = 0; j < W; j++) { bins[j] = __ldcg(h + sbase + j); local += bins[j]; }
            unsigned t = local;
            #pragma unroll
            for (int d = 16; d > 0; d >>= 1) t += __shfl_down_sync(0xffffffffu, t, d);
            if (lane == 0) s_red[wid] = t;
            __syncthreads();
            if (tid == 0) {
                unsigned tot = 0;
                #pragma unroll
                for (int k = 0; k < NT / 32; k++) tot += s_red[k];
                s_total = tot;
            }
            __syncthreads();
            if (s_total == (unsigned)HW) break;
            __nanosleep(128);
            __syncthreads();
        }

        unsigned p = local;
        #pragma unroll
        for (int d = 1; d < 32; d <<= 1) {
            unsigned o = __shfl_up_sync(0xffffffffu, p, d);
            if (lane >= d) p += o;
        }
        if (lane == 31) s_red[wid] = p;
        __syncthreads();
        if (tid == 0) {
            unsigned cum = 0;
            #pragma unroll
            for (int k = 0; k < NT / 32; k++) { unsigned t = s_red[k]; s_red[k] = cum; cum += t; }
        }
        __syncthreads();
        const unsigned pre = p - local + s_red[wid];

        const unsigned ranks[4] = {RANK0, RANK1, RANK2, RANK3};
        #pragma unroll
        for (int t = 0; t < 4; t++) {
            unsigned r = ranks[t];
            if (r >= pre && r < pre + local) {
                unsigned cum = pre;
                #pragma unroll
                for (int j = 0; j < W; j++) {
                    unsigned c = bins[j];
                    if (r < cum + c) {
                        s_vals[t] = ((float)(sbase + j) + 0.5f) * (1.0f / 2048.0f);
                        break;
                    }
                    cum += c;
                }
            }
        }
        __syncthreads();
        if (tid == 0) {
            float blk = 0.25f * s_vals[0] + 0.75f * s_vals[1];
            float wht = 0.75f * s_vals[2] + 0.25f * s_vals[3];
            float m = fminf(1.0f / (wht - blk), 1.5f);
            g_blk[b] = blk;
            g_mult[b] = m;
            s_bm[0] = blk;
            s_bm[1] = m;
            __threadfence();                 // 16 threads chip-wide: negligible
            atomicAdd(&g_flag[b], 1u);       // epoch bump (monotonic, no reset needed)
        }
        // zero this batch's hist for the next replay (sole writer)
        for (int j = tid; j < BINS; j += NT) g_hist[b][j] = 0u;
        __syncthreads();
    } else {
        // ---------------- consumer: wait for epoch bump ----------------
        if (tid == 0) {
            const unsigned init = s_init;
            while (__ldcg(&g_flag[b]) == init) __nanosleep(64);
            s_bm[0] = __ldcg(&g_blk[b]);
            s_bm[1] = __ldcg(&g_mult[b]);
        }
        __syncthreads();
    }

    // ---------------- phase 2: apply own slice ----------------
    const float blk = s_bm[0];
    const float m = s_bm[1];
    const size_t abase = (size_t)b * 3 * (HW / 4);
    const float4* __restrict__ in4 = (const float4*)img + abase;
    float4* __restrict__ o4 = (float4*)out + abase;
    const int per_apply = (3 * (HW / 4)) / CPB;  // 12288 float4
    const int aoff = s * per_apply;

    for (int i = tid; i < per_apply; i += NT) {
        float4 v = in4[aoff + i];
        float4 r;
        r.x = fminf(fmaxf((v.x - blk) * m, 0.0f), 1.0f);
        r.y = fminf(fmaxf((v.y - blk) * m, 0.0f), 1.0f);
        r.z = fminf(fmaxf((v.z - blk) * m, 0.0f), 1.0f);
        r.w = fminf(fmaxf((v.w - blk) * m, 0.0f), 1.0f);
        o4[aoff + i] = r;
    }
}

// ---------------- launch ----------------
extern "C" void kernel_launch(void* const* d_in, const int* in_sizes, int n_in,
                              void* d_out, int out_size) {
    const float* img = (const float*)d_in[0];
    const float* mat = (const float*)d_in[1];
    float* out = (float*)d_out;

    k_fused<<<BATCH * CPB, NT>>>(img, mat, out);
}

// round 14
// speedup vs baseline: 1.0589x; 1.0589x over previous
#include <cuda_runtime.h>

#define BATCH 16
#define HW (1 << 20)
#define BINS 2048               // 11-bit quantization (rel_err 2.3e-4 validated in R12)
#define CHUNKS 64               // yhist CTAs per batch (grid 1024 = full wave)
#define NT 256
#define APB 384                 // apply CTAs per batch

// percentile ranks, n = 1048576 (linear interp):
// blk: 0.25*v[10485] + 0.75*v[10486] ; wht: 0.75*v[1038089] + 0.25*v[1038090]
#define RANK0 10485u
#define RANK1 10486u
#define RANK2 1038089u
#define RANK3 1038090u

// ---------------- device scratch ----------------
__device__ unsigned g_hist[BATCH][BINS];   // 128 KB total, L2-resident
__device__ float    g_blk[BATCH];
__device__ float    g_mult[BATCH];

// ------------- kernel 1: 11-bit luma histogram; chunk-0 CTA per batch selects -------------
__global__ void __launch_bounds__(NT) k_yhist(const float* __restrict__ img,
                                              const float* __restrict__ mat) {
    __shared__ unsigned sh[BINS];
    __shared__ unsigned s_red[NT / 32];
    __shared__ unsigned s_total;
    __shared__ float s_vals[4];
    const int b = blockIdx.y;
    const int chunk = blockIdx.x;
    const int tid = threadIdx.x;
    const int lane = tid & 31;
    const int wid = tid >> 5;

    for (int j = tid; j < BINS; j += NT) sh[j] = 0u;
    __syncthreads();

    const float c0 = mat[0], c1 = mat[1], c2 = mat[2];
    const size_t base = (size_t)b * 3 * HW;
    const float4* __restrict__ R  = (const float4*)(img + base);
    const float4* __restrict__ G  = (const float4*)(img + base + HW);
    const float4* __restrict__ Bc = (const float4*)(img + base + 2 * (size_t)HW);

    const int per_cta = (HW / 4) / CHUNKS;   // 4096 float4
    const int off = chunk * per_cta;

    #pragma unroll 4
    for (int i = tid; i < per_cta; i += NT) {
        float4 r = R[off + i];
        float4 g = G[off + i];
        float4 v = Bc[off + i];
        float y0 = c0 * r.x + c1 * g.x + c2 * v.x;
        float y1 = c0 * r.y + c1 * g.y + c2 * v.y;
        float y2 = c0 * r.z + c1 * g.z + c2 * v.z;
        float y3 = c0 * r.w + c1 * g.w + c2 * v.w;
        unsigned q0 = min((unsigned)(y0 * 2048.0f), BINS - 1u);
        unsigned q1 = min((unsigned)(y1 * 2048.0f), BINS - 1u);
        unsigned q2 = min((unsigned)(y2 * 2048.0f), BINS - 1u);
        unsigned q3 = min((unsigned)(y3 * 2048.0f), BINS - 1u);
        atomicAdd(&sh[q0], 1u);
        atomicAdd(&sh[q1], 1u);
        atomicAdd(&sh[q2], 1u);
        atomicAdd(&sh[q3], 1u);
    }
    __syncthreads();

    for (int j = tid; j < BINS; j += NT) {
        unsigned v = sh[j];
        if (v) atomicAdd(&g_hist[b][j], v);
    }

    if (blockIdx.x != 0) return;

    // ================ producer tail (16 CTAs): fence-free completion + select ================
    const unsigned* __restrict__ h = g_hist[b];
    const int W = BINS / NT;                  // 8 bins per thread
    const int sbase = tid * W;
    unsigned bins[BINS / NT];
    unsigned local;

    // spin: monotone counters sum to exactly HW only when every flush is visible
    for (;;) {
        local = 0;
        #pragma unroll
        for (int j = 0; j < W; j++) { bins[j] = __ldcg(h + sbase + j); local += bins[j]; }
        unsigned s = local;
        #pragma unroll
        for (int d = 16; d > 0; d >>= 1) s += __shfl_down_sync(0xffffffffu, s, d);
        if (lane == 0) s_red[wid] = s;
        __syncthreads();
        if (tid == 0) {
            unsigned tot = 0;
            #pragma unroll
            for (int k = 0; k < NT / 32; k++) tot += s_red[k];
            s_total = tot;
        }
        __syncthreads();
        if (s_total == (unsigned)HW) break;
        __nanosleep(128);
        __syncthreads();
    }

    // block exclusive scan of per-thread totals
    unsigned p = local;
    #pragma unroll
    for (int d = 1; d < 32; d <<= 1) {
        unsigned o = __shfl_up_sync(0xffffffffu, p, d);
        if (lane >= d) p += o;
    }
    if (lane == 31) s_red[wid] = p;
    __syncthreads();
    if (tid == 0) {
        unsigned cum = 0;
        #pragma unroll
        for (int k = 0; k < NT / 32; k++) { unsigned t = s_red[k]; s_red[k] = cum; cum += t; }
    }
    __syncthreads();
    const unsigned pre = p - local + s_red[wid];

    const unsigned ranks[4] = {RANK0, RANK1, RANK2, RANK3};
    #pragma unroll
    for (int t = 0; t < 4; t++) {
        unsigned r = ranks[t];
        if (r >= pre && r < pre + local) {
            unsigned cum = pre;
            #pragma unroll
            for (int j = 0; j < W; j++) {
                unsigned c = bins[j];
                if (r < cum + c) {
                    s_vals[t] = ((float)(sbase + j) + 0.5f) * (1.0f / 2048.0f);
                    break;
                }
                cum += c;
            }
        }
    }
    __syncthreads();
    if (tid == 0) {
        float blk = 0.25f * s_vals[0] + 0.75f * s_vals[1];
        float wht = 0.75f * s_vals[2] + 0.25f * s_vals[3];
        g_blk[b] = blk;
        g_mult[b] = fminf(1.0f / (wht - blk), 1.5f);
    }
    // zero this batch's hist for the next replay (sole writer; batch hist is final)
    for (int j = tid; j < BINS; j += NT) g_hist[b][j] = 0u;
}

// ------------- kernel 2: pure streamer: out = clip((img - blk)*mult, 0, 1) -------------
__global__ void __launch_bounds__(NT) k_apply(const float* __restrict__ img,
                                              float* __restrict__ out) {
    const int b = blockIdx.y;
    const float blk = g_blk[b];
    const float m = g_mult[b];

    const size_t base = (size_t)b * 3 * (HW / 4);
    const float4* __restrict__ in4 = (const float4*)img + base;
    float4* __restrict__ o4 = (float4*)out + base;
    const int n = 3 * (HW / 4);               // 786432 float4 per batch
    const int stride = gridDim.x * NT;

    for (int i = blockIdx.x * NT + threadIdx.x; i < n; i += stride) {
        float4 v = in4[i];
        float4 r;
        r.x = fminf(fmaxf((v.x - blk) * m, 0.0f), 1.0f);
        r.y = fminf(fmaxf((v.y - blk) * m, 0.0f), 1.0f);
        r.z = fminf(fmaxf((v.z - blk) * m, 0.0f), 1.0f);
        r.w = fminf(fmaxf((v.w - blk) * m, 0.0f), 1.0f);
        o4[i] = r;
    }
}

// ---------------- launch ----------------
extern "C" void kernel_launch(void* const* d_in, const int* in_sizes, int n_in,
                              void* d_out, int out_size) {
    const float* img = (const float*)d_in[0];
    const float* mat = (const float*)d_in[1];
    float* out = (float*)d_out;

    dim3 gHist(CHUNKS, BATCH);
    k_yhist<<<gHist, NT>>>(img, mat);
    dim3 gApply(APB, BATCH);
    k_apply<<<gApply, NT>>>(img, out);
}

// round 15
// speedup vs baseline: 1.0817x; 1.0215x over previous
#include <cuda_runtime.h>

#define BATCH 16
#define HW (1 << 20)
#define BINS 2048               // 11-bit quantization (rel_err 2.3e-4 validated)
#define CHUNKS 64               // yhist CTAs per batch (grid 1024 = full wave)
#define NT 256
#define APB 384                 // apply CTAs per batch

// percentile ranks, n = 1048576 (linear interp):
// blk: 0.25*v[10485] + 0.75*v[10486] ; wht: 0.75*v[1038089] + 0.25*v[1038090]
#define RANK0 10485u
#define RANK1 10486u
#define RANK2 1038089u
#define RANK3 1038090u

// ---------------- device scratch ----------------
__device__ unsigned g_hist[BATCH][BINS];   // 128 KB total, L2-resident
__device__ float    g_blk[BATCH];
__device__ float    g_mult[BATCH];

// ------------- kernel 1: 11-bit luma histogram; chunk-0 CTA per batch selects -------------
__global__ void __launch_bounds__(NT) k_yhist(const float* __restrict__ img,
                                              const float* __restrict__ mat) {
    __shared__ unsigned sh[BINS];
    __shared__ unsigned s_red[NT / 32];
    __shared__ unsigned s_total;
    __shared__ float s_vals[4];
    const int b = blockIdx.y;
    const int chunk = blockIdx.x;
    const int tid = threadIdx.x;
    const int lane = tid & 31;
    const int wid = tid >> 5;

    for (int j = tid; j < BINS; j += NT) sh[j] = 0u;
    __syncthreads();

    const float c0 = mat[0], c1 = mat[1], c2 = mat[2];
    const size_t base = (size_t)b * 3 * HW;
    const float4* __restrict__ R  = (const float4*)(img + base);
    const float4* __restrict__ G  = (const float4*)(img + base + HW);
    const float4* __restrict__ Bc = (const float4*)(img + base + 2 * (size_t)HW);

    const int per_cta = (HW / 4) / CHUNKS;   // 4096 float4
    const int off = chunk * per_cta;

    #pragma unroll 4
    for (int i = tid; i < per_cta; i += NT) {
        float4 r = R[off + i];
        float4 g = G[off + i];
        float4 v = Bc[off + i];
        float y0 = c0 * r.x + c1 * g.x + c2 * v.x;
        float y1 = c0 * r.y + c1 * g.y + c2 * v.y;
        float y2 = c0 * r.z + c1 * g.z + c2 * v.z;
        float y3 = c0 * r.w + c1 * g.w + c2 * v.w;
        unsigned q0 = min((unsigned)(y0 * 2048.0f), BINS - 1u);
        unsigned q1 = min((unsigned)(y1 * 2048.0f), BINS - 1u);
        unsigned q2 = min((unsigned)(y2 * 2048.0f), BINS - 1u);
        unsigned q3 = min((unsigned)(y3 * 2048.0f), BINS - 1u);
        atomicAdd(&sh[q0], 1u);
        atomicAdd(&sh[q1], 1u);
        atomicAdd(&sh[q2], 1u);
        atomicAdd(&sh[q3], 1u);
    }
    __syncthreads();

    for (int j = tid; j < BINS; j += NT) {
        unsigned v = sh[j];
        if (v) atomicAdd(&g_hist[b][j], v);
    }
    __syncthreads();

    // PDL: this CTA's contribution is flushed — allow the apply grid to launch.
    // Producer CTAs continue with the select tail afterward (legal post-trigger work).
    asm volatile("griddepcontrol.launch_dependents;" ::: "memory");

    if (blockIdx.x != 0) return;

    // ================ producer tail (16 CTAs): fence-free completion + select ================
    const unsigned* __restrict__ h = g_hist[b];
    const int W = BINS / NT;                  // 8 bins per thread
    const int sbase = tid * W;
    unsigned bins[BINS / NT];
    unsigned local;

    // spin: monotone counters sum to exactly HW only when every flush is visible
    for (;;) {
        local = 0;
        #pragma unroll
        for (int j = 0; j < W; j++) { bins[j] = __ldcg(h + sbase + j); local += bins[j]; }
        unsigned s = local;
        #pragma unroll
        for (int d = 16; d > 0; d >>= 1) s += __shfl_down_sync(0xffffffffu, s, d);
        if (lane == 0) s_red[wid] = s;
        __syncthreads();
        if (tid == 0) {
            unsigned tot = 0;
            #pragma unroll
            for (int k = 0; k < NT / 32; k++) tot += s_red[k];
            s_total = tot;
        }
        __syncthreads();
        if (s_total == (unsigned)HW) break;
        __nanosleep(128);
        __syncthreads();
    }

    // block exclusive scan of per-thread totals
    unsigned p = local;
    #pragma unroll
    for (int d = 1; d < 32; d <<= 1) {
        unsigned o = __shfl_up_sync(0xffffffffu, p, d);
        if (lane >= d) p += o;
    }
    if (lane == 31) s_red[wid] = p;
    __syncthreads();
    if (tid == 0) {
        unsigned cum = 0;
        #pragma unroll
        for (int k = 0; k < NT / 32; k++) { unsigned t = s_red[k]; s_red[k] = cum; cum += t; }
    }
    __syncthreads();
    const unsigned pre = p - local + s_red[wid];

    const unsigned ranks[4] = {RANK0, RANK1, RANK2, RANK3};
    #pragma unroll
    for (int t = 0; t < 4; t++) {
        unsigned r = ranks[t];
        if (r >= pre && r < pre + local) {
            unsigned cum = pre;
            #pragma unroll
            for (int j = 0; j < W; j++) {
                unsigned c = bins[j];
                if (r < cum + c) {
                    s_vals[t] = ((float)(sbase + j) + 0.5f) * (1.0f / 2048.0f);
                    break;
                }
                cum += c;
            }
        }
    }
    __syncthreads();
    if (tid == 0) {
        float blk = 0.25f * s_vals[0] + 0.75f * s_vals[1];
        float wht = 0.75f * s_vals[2] + 0.25f * s_vals[3];
        g_blk[b] = blk;
        g_mult[b] = fminf(1.0f / (wht - blk), 1.5f);
    }
    // zero this batch's hist for the next replay (sole writer; batch hist is final)
    for (int j = tid; j < BINS; j += NT) g_hist[b][j] = 0u;
}

// ------------- kernel 2: PDL streamer: prefetch -> griddepcontrol.wait -> apply -------------
// Per-thread work is exactly 8 float4 (786432 / (APB*NT) = 8): no bounds checks needed.
__global__ void __launch_bounds__(NT) k_apply(const float* __restrict__ img,
                                              float* __restrict__ out) {
    const int b = blockIdx.y;
    const size_t base = (size_t)b * 3 * (HW / 4);
    const float4* __restrict__ in4 = (const float4*)img + base;
    float4* __restrict__ o4 = (float4*)out + base;
    const int stride = APB * NT;              // 98304
    const int i0 = blockIdx.x * NT + threadIdx.x;

    // prefetch the first two loads — independent of blk/mult, overlaps the
    // primary grid's producer tail and this grid's launch latency
    float4 v0 = in4[i0];
    float4 v1 = in4[i0 + stride];

    asm volatile("griddepcontrol.wait;" ::: "memory");

    const float blk = g_blk[b];
    const float m = g_mult[b];

    float4 r;
    r.x = fminf(fmaxf((v0.x - blk) * m, 0.0f), 1.0f);
    r.y = fminf(fmaxf((v0.y - blk) * m, 0.0f), 1.0f);
    r.z = fminf(fmaxf((v0.z - blk) * m, 0.0f), 1.0f);
    r.w = fminf(fmaxf((v0.w - blk) * m, 0.0f), 1.0f);
    o4[i0] = r;
    r.x = fminf(fmaxf((v1.x - blk) * m, 0.0f), 1.0f);
    r.y = fminf(fmaxf((v1.y - blk) * m, 0.0f), 1.0f);
    r.z = fminf(fmaxf((v1.z - blk) * m, 0.0f), 1.0f);
    r.w = fminf(fmaxf((v1.w - blk) * m, 0.0f), 1.0f);
    o4[i0 + stride] = r;

    #pragma unroll
    for (int k = 2; k < 8; k++) {
        const int i = i0 + k * stride;
        float4 v = in4[i];
        float4 q;
        q.x = fminf(fmaxf((v.x - blk) * m, 0.0f), 1.0f);
        q.y = fminf(fmaxf((v.y - blk) * m, 0.0f), 1.0f);
        q.z = fminf(fmaxf((v.z - blk) * m, 0.0f), 1.0f);
        q.w = fminf(fmaxf((v.w - blk) * m, 0.0f), 1.0f);
        o4[i] = q;
    }
}

// ---------------- launch ----------------
extern "C" void kernel_launch(void* const* d_in, const int* in_sizes, int n_in,
                              void* d_out, int out_size) {
    const float* img = (const float*)d_in[0];
    const float* mat = (const float*)d_in[1];
    float* out = (float*)d_out;

    dim3 gHist(CHUNKS, BATCH);
    k_yhist<<<gHist, NT>>>(img, mat);

    // apply with programmatic dependent launch (overlaps yhist's tail)
    cudaLaunchConfig_t cfg = {};
    cfg.gridDim = dim3(APB, BATCH);
    cfg.blockDim = dim3(NT);
    cfg.dynamicSmemBytes = 0;
    cfg.stream = 0;
    cudaLaunchAttribute attrs[1];
    attrs[0].id = cudaLaunchAttributeProgrammaticStreamSerialization;
    attrs[0].val.programmaticStreamSerializationAllowed = 1;
    cfg.attrs = attrs;
    cfg.numAttrs = 1;
    cudaLaunchKernelEx(&cfg, k_apply, img, out);
}